// round 8
// baseline (speedup 1.0000x reference)
#include <cuda_runtime.h>

#define BB 16
#define NN 4096
#define SS 512
#define NSAMP 32
#define PPOS (BB*SS*NSAMP)   // 262144 positions
#define NGRP (BB*SS)         // 8192 (b,s) groups
#define NPERS 296            // persistent grid (2 CTAs x 148 SMs)

// ---------------- device scratch ----------------
__device__ float g_feat[6*PPOS];        // grouped features [c][p]
__device__ float g_x2[64*PPOS];         // layer2 raw conv out
__device__ float2 g_pool[128*NGRP];     // {max,min} of raw layer3 per group
__device__ float g_stats[384];          // [0..127] L2 sum/sumsq, [128..383] L3
__device__ float g_gram[27*32];         // 27 moments, line-padded (864 floats)
__device__ float4 g_new[NGRP];          // centroid x,y,z,|c|^2

// ---------------- helpers ----------------
__device__ __forceinline__ unsigned long long fma2(unsigned long long a,
                                                   unsigned long long b,
                                                   unsigned long long c) {
    unsigned long long d;
    asm("fma.rn.f32x2 %0, %1, %2, %3;" : "=l"(d) : "l"(a), "l"(b), "l"(c));
    return d;
}
__device__ __forceinline__ unsigned long long pack2(float lo, float hi) {
    unsigned long long d;
    asm("mov.b64 %0, {%1, %2};" : "=l"(d) : "f"(lo), "f"(hi));
    return d;
}
__device__ __forceinline__ float2 unpack2(unsigned long long v) {
    float2 r;
    asm("mov.b64 {%0, %1}, %2;" : "=f"(r.x), "=f"(r.y) : "l"(v));
    return r;
}
__device__ __forceinline__ void cp_async16(void* smem_dst, const void* gmem_src) {
    unsigned s = (unsigned)__cvta_generic_to_shared(smem_dst);
    asm volatile("cp.async.cg.shared.global [%0], [%1], 16;" :: "r"(s), "l"(gmem_src) : "memory");
}
__device__ __forceinline__ void cp_commit() { asm volatile("cp.async.commit_group;" ::: "memory"); }
__device__ __forceinline__ void cp_wait0()  { asm volatile("cp.async.wait_group 0;"  ::: "memory"); }

// FPS: 1 CTA/batch, 1024 threads, 4 pts/thread, tree argmax, 1 barrier/iter.
__global__ __launch_bounds__(1024) void fps_kernel(const float* __restrict__ xyz,
                                                   float* __restrict__ out_newxyz)
{
    extern __shared__ float sh[];
    float* xs = sh; float* ys = sh + NN; float* zs = sh + 2*NN;
    __shared__ unsigned long long wkey[2][32];
    const int b = blockIdx.x;
    const int t = threadIdx.x;
    const int lane = t & 31, wid = t >> 5;
    const float* X = xyz + b*3*NN;

    if (b == 0) {   // re-zero ALL accumulator scratch every launch (replay-safe)
        if (t < 384)   g_stats[t] = 0.0f;
        if (t < 27*32) g_gram[t]  = 0.0f;
    }

    float px[4], py[4], pz[4], dist[4];
#pragma unroll
    for (int k = 0; k < 4; ++k) {
        int n = t + k*1024;
        px[k] = X[n]; py[k] = X[NN+n]; pz[k] = X[2*NN+n];
        xs[n] = px[k]; ys[n] = py[k]; zs[n] = pz[k];
        dist[k] = 1e10f;
    }
    __syncthreads();

    int far = 0;
    for (int s = 0; s < SS; ++s) {
        float cx = xs[far], cy = ys[far], cz = zs[far];
        if (t == 0) {
            out_newxyz[(b*3+0)*SS + s] = cx;
            out_newxyz[(b*3+1)*SS + s] = cy;
            out_newxyz[(b*3+2)*SS + s] = cz;
            float sn = fmaf(cz,cz,fmaf(cy,cy,cx*cx));
            g_new[b*SS+s] = make_float4(cx,cy,cz,sn);
        }
        float nd[4];
#pragma unroll
        for (int k = 0; k < 4; ++k) {
            float dx = px[k]-cx, dy = py[k]-cy, dz = pz[k]-cz;
            float d = fmaf(dz,dz,fmaf(dy,dy,dx*dx));
            nd[k] = fminf(dist[k], d);
            dist[k] = nd[k];
        }
        float m0 = nd[0]; int j0 = t;
        { bool c = nd[1] > m0; m0 = c ? nd[1] : m0; j0 = c ? t+1024 : j0; }
        float m1 = nd[2]; int j1 = t+2048;
        { bool c = nd[3] > m1; m1 = c ? nd[3] : m1; j1 = c ? t+3072 : j1; }
        bool c2 = m1 > m0;
        float bd = c2 ? m1 : m0; int bi = c2 ? j1 : j0;

        unsigned db = __float_as_uint(bd);
        unsigned wm = __reduce_max_sync(0xFFFFFFFFu, db);
        unsigned lo = __reduce_max_sync(0xFFFFFFFFu, (db == wm) ? ~(unsigned)bi : 0u);
        if (lane == 0) wkey[s & 1][wid] = ((unsigned long long)wm << 32) | lo;
        __syncthreads();
        unsigned long long k2 = wkey[s & 1][lane];
        unsigned hi = (unsigned)(k2 >> 32), l2 = (unsigned)k2;
        unsigned m2 = __reduce_max_sync(0xFFFFFFFFu, hi);
        unsigned lw = __reduce_max_sync(0xFFFFFFFFu, (hi == m2) ? l2 : 0u);
        far = (int)(~lw);
    }
}

// Ball query + gather + fused 27-moment accumulation. One warp per centroid.
__global__ __launch_bounds__(256) void group_kernel(const float* __restrict__ xyz,
                                                    const float* __restrict__ pts)
{
    __shared__ int sel[8][NSAMP];
    __shared__ float red[27];
    const int lane = threadIdx.x & 31, w = threadIdx.x >> 5;
    const int tid = threadIdx.x;
    if (tid < 27) red[tid] = 0.0f;
    __syncthreads();

    const int id = blockIdx.x*8 + w;
    const int b = id >> 9;
    const float4 c4 = g_new[id];
    const float* X = xyz + b*3*NN;
    const float* Q = pts + b*3*NN;
    const float R2 = (float)(0.4*0.4);

    int cnt = 0;
    for (int base = 0; base < NN && cnt < NSAMP; base += 32) {
        int n = base + lane;
        float x = X[n], y = X[NN+n], z = X[2*NN+n];
        float sx  = fmaf(z,z,fmaf(y,y,x*x));
        float dot = fmaf(z,c4.z,fmaf(y,c4.y,x*c4.x));
        float sq  = (c4.w + sx) - 2.0f*dot;
        bool pred = (sq <= R2);
        unsigned m = __ballot_sync(0xFFFFFFFFu, pred);
        if (pred) {
            int pos = cnt + __popc(m & ((1u << lane) - 1u));
            if (pos < NSAMP) sel[w][pos] = n;
        }
        cnt += __popc(m);
    }
    __syncwarp();
    int total = cnt < NSAMP ? cnt : NSAMP;
    int idx = sel[w][lane < total ? lane : 0];

    float f[6];
    f[0] = X[idx]      - c4.x;
    f[1] = X[NN+idx]   - c4.y;
    f[2] = X[2*NN+idx] - c4.z;
    f[3] = Q[idx];
    f[4] = Q[NN+idx];
    f[5] = Q[2*NN+idx];

    int p = id*NSAMP + lane;
#pragma unroll
    for (int c = 0; c < 6; ++c) g_feat[c*PPOS + p] = f[c];

    float v[27];
#pragma unroll
    for (int c = 0; c < 6; ++c) v[c] = f[c];
    {
        int k = 6;
#pragma unroll
        for (int i = 0; i < 6; ++i)
#pragma unroll
            for (int j = i; j < 6; ++j) { v[k] = f[i]*f[j]; ++k; }
    }
#pragma unroll
    for (int off = 16; off; off >>= 1)
#pragma unroll
        for (int i = 0; i < 27; ++i)
            v[i] += __shfl_down_sync(0xFFFFFFFFu, v[i], off);
    if (lane == 0)
#pragma unroll
        for (int i = 0; i < 27; ++i) atomicAdd(&red[i], v[i]);
    __syncthreads();
    if (tid < 27) atomicAdd(&g_gram[tid*32], red[tid]);
}

// PERSISTENT fused layer1+layer2: weights + BN1 loaded once, tiles looped.
__global__ __launch_bounds__(256,2) void fused12_kernel(const float* __restrict__ w0,
                                                        const float* __restrict__ b0,
                                                        const float* __restrict__ g0,
                                                        const float* __restrict__ beta0,
                                                        const float* __restrict__ w1,
                                                        const float* __restrict__ b1)
{
    extern __shared__ char smraw[];
    unsigned long long* w0d = (unsigned long long*)smraw;            // 384 ull
    unsigned long long* w1d = (unsigned long long*)(smraw + 3072);   // 4096 ull
    float* sab = (float*)(smraw + 35840);                            // 128 (BN1 A/B)
    float* tf  = (float*)(smraw + 36352);                            // 6 x 256
    float* tx  = (float*)(smraw + 42496);                            // 64 x 256
    float* red = (float*)(smraw + 108032);                           // 128 (BN2 partials)
    const int tid  = threadIdx.x;
    const int lane = tid & 31, wid = tid >> 5;
    const int ob = wid * 8;

    if (tid < 128) red[tid] = 0.0f;
    // analytic BN1 (once per CTA)
    if (tid < 64) {
        const int o = tid;
        float w[6];
#pragma unroll
        for (int c = 0; c < 6; ++c) w[c] = w0[o*6+c];
        float wS = 0.0f;
#pragma unroll
        for (int c = 0; c < 6; ++c) wS = fmaf(w[c], g_gram[c*32], wS);
        float quad = 0.0f; int idx = 6;
#pragma unroll
        for (int i = 0; i < 6; ++i)
#pragma unroll
            for (int j = i; j < 6; ++j) {
                float coef = (i == j) ? 1.0f : 2.0f;
                quad = fmaf(coef * w[i] * w[j], g_gram[idx*32], quad);
                ++idx;
            }
        float bo = b0[o];
        const float invP = 1.0f / (float)PPOS;
        float m   = fmaf(wS, invP, bo);
        float Ex2 = quad*invP + 2.0f*bo*wS*invP + bo*bo;
        float A = g0[o] * rsqrtf(Ex2 - m*m + 1e-5f);
        sab[o]    = A;
        sab[64+o] = fmaf(bo - m, A, beta0[o]);
    }
    for (int i = tid; i < 384; i += 256) { float v = w0[i]; w0d[i] = pack2(v,v); }
    for (int i = tid; i < 1024; i += 256) {
        float4 v = ((const float4*)w1)[i];
        w1d[i*4+0] = pack2(v.x,v.x); w1d[i*4+1] = pack2(v.y,v.y);
        w1d[i*4+2] = pack2(v.z,v.z); w1d[i*4+3] = pack2(v.w,v.w);
    }

    for (int tile = blockIdx.x; tile < PPOS/256; tile += NPERS) {
        const int p0 = tile * 256;
        __syncthreads();   // prev stage-B done reading tx; tf free
        for (int i = tid; i < 384; i += 256) {
            int c = i >> 6, pp = (i & 63) * 4;
            *(float4*)(tf + c*256 + pp) = *(const float4*)(g_feat + c*PPOS + p0 + pp);
        }
        __syncthreads();

        // ---- stage A: 6 -> 64 ----
        {
            unsigned long long a[8][4];
#pragma unroll
            for (int j = 0; j < 8; ++j)
#pragma unroll
                for (int q = 0; q < 4; ++q) a[j][q] = 0ull;
#pragma unroll
            for (int c = 0; c < 6; ++c) {
                ulonglong2 iv0 = *(const ulonglong2*)(tf + c*256 + lane*4);
                ulonglong2 iv1 = *(const ulonglong2*)(tf + c*256 + 128 + lane*4);
#pragma unroll
                for (int j = 0; j < 8; ++j) {
                    unsigned long long wv = w0d[(ob+j)*6 + c];
                    a[j][0] = fma2(wv, iv0.x, a[j][0]);
                    a[j][1] = fma2(wv, iv0.y, a[j][1]);
                    a[j][2] = fma2(wv, iv1.x, a[j][2]);
                    a[j][3] = fma2(wv, iv1.y, a[j][3]);
                }
            }
#pragma unroll
            for (int j = 0; j < 8; ++j) {
                float A = sab[ob+j], Bv = sab[64+ob+j];
#pragma unroll
                for (int s2 = 0; s2 < 2; ++s2) {
                    float2 u = unpack2(a[j][s2*2+0]);
                    float2 v = unpack2(a[j][s2*2+1]);
                    float4 o4;
                    o4.x = fmaxf(fmaf(u.x,A,Bv),0.f);
                    o4.y = fmaxf(fmaf(u.y,A,Bv),0.f);
                    o4.z = fmaxf(fmaf(v.x,A,Bv),0.f);
                    o4.w = fmaxf(fmaf(v.y,A,Bv),0.f);
                    *(float4*)(tx + (ob+j)*256 + s2*128 + lane*4) = o4;
                }
            }
        }
        __syncthreads();

        // ---- stage B: 64 -> 64 ----
        unsigned long long acc[8][4];
#pragma unroll
        for (int j = 0; j < 8; ++j) {
            float bv = b1[ob+j];
            unsigned long long pb = pack2(bv,bv);
#pragma unroll
            for (int q = 0; q < 4; ++q) acc[j][q] = pb;
        }
#pragma unroll 4
        for (int c2 = 0; c2 < 32; ++c2) {
            const float* base = tx + c2*512;
            ulonglong2 a0 = *(const ulonglong2*)(base + lane*4);
            ulonglong2 a1 = *(const ulonglong2*)(base + 128 + lane*4);
            ulonglong2 c0 = *(const ulonglong2*)(base + 256 + lane*4);
            ulonglong2 c1 = *(const ulonglong2*)(base + 384 + lane*4);
#pragma unroll
            for (int j = 0; j < 8; ++j) {
                ulonglong2 wp = *(const ulonglong2*)(w1d + (ob+j)*64 + c2*2);
                acc[j][0] = fma2(wp.x, a0.x, acc[j][0]);
                acc[j][1] = fma2(wp.x, a0.y, acc[j][1]);
                acc[j][2] = fma2(wp.x, a1.x, acc[j][2]);
                acc[j][3] = fma2(wp.x, a1.y, acc[j][3]);
                acc[j][0] = fma2(wp.y, c0.x, acc[j][0]);
                acc[j][1] = fma2(wp.y, c0.y, acc[j][1]);
                acc[j][2] = fma2(wp.y, c1.x, acc[j][2]);
                acc[j][3] = fma2(wp.y, c1.y, acc[j][3]);
            }
        }
#pragma unroll
        for (int j = 0; j < 8; ++j) {
            float2 u0 = unpack2(acc[j][0]), u1 = unpack2(acc[j][1]);
            float2 v0 = unpack2(acc[j][2]), v1 = unpack2(acc[j][3]);
            float4 o0 = make_float4(u0.x,u0.y,u1.x,u1.y);
            float4 o1 = make_float4(v0.x,v0.y,v1.x,v1.y);
            *(float4*)(g_x2 + (size_t)(ob+j)*PPOS + p0 + lane*4)       = o0;
            *(float4*)(g_x2 + (size_t)(ob+j)*PPOS + p0 + 128 + lane*4) = o1;
            float sm1 = ((o0.x+o0.y)+(o0.z+o0.w)) + ((o1.x+o1.y)+(o1.z+o1.w));
            float sq  = o0.x*o0.x+o0.y*o0.y+o0.z*o0.z+o0.w*o0.w
                      + o1.x*o1.x+o1.y*o1.y+o1.z*o1.z+o1.w*o1.w;
#pragma unroll
            for (int off = 16; off; off >>= 1) {
                sm1 += __shfl_down_sync(0xFFFFFFFFu, sm1, off);
                sq  += __shfl_down_sync(0xFFFFFFFFu, sq,  off);
            }
            if (lane == 0) {        // unique (warp,j) writer -> no atomic
                red[ob+j]    += sm1;
                red[64+ob+j] += sq;
            }
        }
    }
    __syncthreads();
    if (tid < 128) atomicAdd(&g_stats[tid], red[tid]);
}

// PERSISTENT layer3 (64->128): weights once, cp.async-pipelined x2 tiles,
// inline BN2 fold, smem BN3 stat accumulation, {max,min} pooling.
__global__ __launch_bounds__(256,2) void mlp3_kernel(const float* __restrict__ w2,
                                                     const float* __restrict__ b2,
                                                     const float* __restrict__ g1,
                                                     const float* __restrict__ beta1)
{
    extern __shared__ char smraw[];
    unsigned long long* wd = (unsigned long long*)smraw;   // 8192 ull = 64KB
    float* sab = (float*)(smraw + 65536);                  // 128 (BN2 A/B)
    float* red = (float*)(smraw + 66048);                  // 256 (BN3 partials)
    float* tx  = (float*)(smraw + 67072);                  // 64 x 128 = 32KB
    const int tid  = threadIdx.x;
    const int lane = tid & 31, wid = tid >> 5;
    const int ob = wid * 16;

    red[tid] = 0.0f;
    if (tid < 64) {
        const float invP = 1.0f / (float)PPOS;
        float mean = g_stats[tid]    * invP;
        float var  = g_stats[64+tid] * invP - mean*mean;
        float A = g1[tid] * rsqrtf(var + 1e-5f);
        sab[tid]    = A;
        sab[64+tid] = fmaf(-mean, A, beta1[tid]);
    }
    for (int i = tid; i < 2048; i += 256) {
        float4 v = ((const float4*)w2)[i];
        wd[i*4+0] = pack2(v.x,v.x); wd[i*4+1] = pack2(v.y,v.y);
        wd[i*4+2] = pack2(v.z,v.z); wd[i*4+3] = pack2(v.w,v.w);
    }

    // prefetch first tile (raw x2 -> tx)
    int tile = blockIdx.x;
#pragma unroll
    for (int k = 0; k < 8; ++k) {
        int i = tid + k*256;            // 2048 float4 chunks
        int c = i >> 5, pp = (i & 31) * 4;
        cp_async16(tx + c*128 + pp, g_x2 + (size_t)c*PPOS + tile*128 + pp);
    }
    cp_commit(); cp_wait0();
    __syncthreads();

    while (tile < PPOS/128) {
        // in-place BN2 affine + relu transform
        for (int k = 0; k < 8; ++k) {
            int i = tid + k*256;
            int c = i >> 5, pp = (i & 31) * 4;
            float A = sab[c], Bv = sab[64+c];
            float4 v = *(float4*)(tx + c*128 + pp);
            v.x = fmaxf(fmaf(v.x,A,Bv),0.f); v.y = fmaxf(fmaf(v.y,A,Bv),0.f);
            v.z = fmaxf(fmaf(v.z,A,Bv),0.f); v.w = fmaxf(fmaf(v.w,A,Bv),0.f);
            *(float4*)(tx + c*128 + pp) = v;
        }
        __syncthreads();

        unsigned long long acc[16][2];
#pragma unroll
        for (int j = 0; j < 16; ++j) {
            float bv = b2[ob+j];
            unsigned long long pb = pack2(bv,bv);
            acc[j][0] = pb; acc[j][1] = pb;
        }
#pragma unroll 4
        for (int c2 = 0; c2 < 32; ++c2) {
            const float* base = tx + c2*256;
            ulonglong2 d0 = *(const ulonglong2*)(base + lane*4);
            ulonglong2 d1 = *(const ulonglong2*)(base + 128 + lane*4);
#pragma unroll
            for (int j = 0; j < 16; ++j) {
                ulonglong2 wp = *(const ulonglong2*)(wd + (ob+j)*64 + c2*2);
                acc[j][0] = fma2(wp.x, d0.x, acc[j][0]);
                acc[j][1] = fma2(wp.x, d0.y, acc[j][1]);
                acc[j][0] = fma2(wp.y, d1.x, acc[j][0]);
                acc[j][1] = fma2(wp.y, d1.y, acc[j][1]);
            }
        }
        __syncthreads();   // all warps done reading tx

        // start fetching next tile while we run the shuffle epilogue
        int next = tile + NPERS;
        if (next < PPOS/128) {
#pragma unroll
            for (int k = 0; k < 8; ++k) {
                int i = tid + k*256;
                int c = i >> 5, pp = (i & 31) * 4;
                cp_async16(tx + c*128 + pp, g_x2 + (size_t)c*PPOS + next*128 + pp);
            }
        }
        cp_commit();

#pragma unroll
        for (int j = 0; j < 16; ++j) {
            float2 u = unpack2(acc[j][0]), v = unpack2(acc[j][1]);
            float f0 = u.x, f1 = u.y, f2 = v.x, f3 = v.y;
            float sm1 = (f0+f1)+(f2+f3);
            float sq  = f0*f0+f1*f1+f2*f2+f3*f3;
#pragma unroll
            for (int off = 16; off; off >>= 1) {
                sm1 += __shfl_down_sync(0xFFFFFFFFu, sm1, off);
                sq  += __shfl_down_sync(0xFFFFFFFFu, sq,  off);
            }
            if (lane == 0) {       // unique (warp,j) writer -> plain accumulate
                red[ob+j]     += sm1;
                red[128+ob+j] += sq;
            }
            float mx = fmaxf(fmaxf(f0,f1), fmaxf(f2,f3));
            float mn = fminf(fminf(f0,f1), fminf(f2,f3));
#pragma unroll
            for (int dlt = 1; dlt < 8; dlt <<= 1) {
                mx = fmaxf(mx, __shfl_xor_sync(0xFFFFFFFFu, mx, dlt));
                mn = fminf(mn, __shfl_xor_sync(0xFFFFFFFFu, mn, dlt));
            }
            if ((lane & 7) == 0) {
                int gid = tile*4 + (lane >> 3);
                g_pool[(ob+j)*NGRP + gid] = make_float2(mx, mn);
            }
        }
        cp_wait0();
        __syncthreads();
        tile = next;
    }
    __syncthreads();
    atomicAdd(&g_stats[128 + tid], red[tid]);
}

// Final: inline BN3 fold + affine+relu on pooled max/min. One CTA per (b,o).
__global__ __launch_bounds__(256) void final_kernel(float* __restrict__ out,
                                                    const float* __restrict__ g2,
                                                    const float* __restrict__ beta2)
{
    __shared__ float sA, sB;
    const int o = blockIdx.x & 127;
    const int b = blockIdx.x >> 7;
    if (threadIdx.x == 0) {
        const float invP = 1.0f / (float)PPOS;
        float mean = g_stats[128+o] * invP;
        float var  = g_stats[256+o] * invP - mean*mean;
        float A = g2[o] * rsqrtf(var + 1e-5f);
        sA = A; sB = fmaf(-mean, A, beta2[o]);
    }
    __syncthreads();
    float A = sA, Bv = sB;
    int s = threadIdx.x * 2;
    float2 p0 = g_pool[o*NGRP + b*SS + s];
    float2 p1 = g_pool[o*NGRP + b*SS + s + 1];
    float v0 = (A >= 0.0f) ? p0.x : p0.y;
    float v1 = (A >= 0.0f) ? p1.x : p1.y;
    float2 r;
    r.x = fmaxf(fmaf(v0, A, Bv), 0.0f);
    r.y = fmaxf(fmaf(v1, A, Bv), 0.0f);
    *(float2*)(out + ((b*128 + o) << 9) + s) = r;
}

// ---------------- launch ----------------
extern "C" void kernel_launch(void* const* d_in, const int* in_sizes, int n_in,
                              void* d_out, int out_size)
{
    const float* xyz = (const float*)d_in[0];
    const float* pts = (const float*)d_in[1];
    const float* w0  = (const float*)d_in[2];
    const float* b0  = (const float*)d_in[3];
    const float* gm0 = (const float*)d_in[4];
    const float* be0 = (const float*)d_in[5];
    const float* w1  = (const float*)d_in[6];
    const float* b1  = (const float*)d_in[7];
    const float* gm1 = (const float*)d_in[8];
    const float* be1 = (const float*)d_in[9];
    const float* w2  = (const float*)d_in[10];
    const float* b2  = (const float*)d_in[11];
    const float* gm2 = (const float*)d_in[12];
    const float* be2 = (const float*)d_in[13];
    float* out = (float*)d_out;

    cudaFuncSetAttribute(fps_kernel,     cudaFuncAttributeMaxDynamicSharedMemorySize, 49152);
    cudaFuncSetAttribute(fused12_kernel, cudaFuncAttributeMaxDynamicSharedMemorySize, 108544);
    cudaFuncSetAttribute(mlp3_kernel,    cudaFuncAttributeMaxDynamicSharedMemorySize, 99840);

    fps_kernel<<<BB, 1024, 49152>>>(xyz, out);
    group_kernel<<<(BB*SS)/8, 256>>>(xyz, pts);
    fused12_kernel<<<NPERS, 256, 108544>>>(w0, b0, gm0, be0, w1, b1);
    mlp3_kernel<<<NPERS, 256, 99840>>>(w2, b2, gm1, be1);
    final_kernel<<<BB*128, 256>>>(out + BB*3*SS, gm2, be2);
}

// round 9
// speedup vs baseline: 1.1065x; 1.1065x over previous
#include <cuda_runtime.h>

#define BB 16
#define NN 4096
#define SS 512
#define NSAMP 32
#define PPOS (BB*SS*NSAMP)   // 262144 positions
#define NGRP (BB*SS)         // 8192 (b,s) groups
#define NPERS 296            // persistent grid (2 CTAs x 148 SMs)

// ---------------- device scratch ----------------
__device__ float g_feat[6*PPOS];        // grouped features [c][p]
__device__ float g_x2[64*PPOS];         // layer2 raw conv out
__device__ float2 g_pool[128*NGRP];     // {max,min} of raw layer3 per group
__device__ float g_stats[384];          // [0..127] L2 sum/sumsq, [128..383] L3
__device__ float g_gram[27*32];         // 27 moments, line-padded (864 floats)
__device__ float4 g_new[NGRP];          // centroid x,y,z,|c|^2

// ---------------- helpers ----------------
__device__ __forceinline__ unsigned long long fma2(unsigned long long a,
                                                   unsigned long long b,
                                                   unsigned long long c) {
    unsigned long long d;
    asm("fma.rn.f32x2 %0, %1, %2, %3;" : "=l"(d) : "l"(a), "l"(b), "l"(c));
    return d;
}
__device__ __forceinline__ unsigned long long add2(unsigned long long a,
                                                   unsigned long long b) {
    unsigned long long d;
    asm("add.rn.f32x2 %0, %1, %2;" : "=l"(d) : "l"(a), "l"(b));
    return d;
}
__device__ __forceinline__ unsigned long long mul2(unsigned long long a,
                                                   unsigned long long b) {
    unsigned long long d;
    asm("mul.rn.f32x2 %0, %1, %2;" : "=l"(d) : "l"(a), "l"(b));
    return d;
}
__device__ __forceinline__ unsigned long long pack2(float lo, float hi) {
    unsigned long long d;
    asm("mov.b64 %0, {%1, %2};" : "=l"(d) : "f"(lo), "f"(hi));
    return d;
}
__device__ __forceinline__ float2 unpack2(unsigned long long v) {
    float2 r;
    asm("mov.b64 {%0, %1}, %2;" : "=f"(r.x), "=f"(r.y) : "l"(v));
    return r;
}
__device__ __forceinline__ void cp_async16(void* smem_dst, const void* gmem_src) {
    unsigned s = (unsigned)__cvta_generic_to_shared(smem_dst);
    asm volatile("cp.async.cg.shared.global [%0], [%1], 16;" :: "r"(s), "l"(gmem_src) : "memory");
}
__device__ __forceinline__ void cp_commit() { asm volatile("cp.async.commit_group;" ::: "memory"); }
__device__ __forceinline__ void cp_wait0()  { asm volatile("cp.async.wait_group 0;"  ::: "memory"); }

// FPS: 1 CTA/batch, 512 threads, 8 pts/thread packed as f32x2 pairs.
// Same FADD/FFMA/FMNMX rounding sequence as the verified scalar version.
__global__ __launch_bounds__(512) void fps_kernel(const float* __restrict__ xyz,
                                                  float* __restrict__ out_newxyz)
{
    extern __shared__ float sh[];
    float4* pts4 = (float4*)sh;            // negated coords, 4096 x 16B
    float4* cbuf = (float4*)(sh + 4*NN);   // 512 x 16B (negated centroids)
    __shared__ unsigned long long wkey[2][16];
    const int b = blockIdx.x, t = threadIdx.x;
    const int lane = t & 31, wid = t >> 5;
    const float* X = xyz + b*3*NN;

    if (b == 0) {   // re-zero ALL accumulator scratch every launch (replay-safe)
        if (t < 384) g_stats[t] = 0.0f;
        for (int i = t; i < 27*32; i += 512) g_gram[i] = 0.0f;
    }

    float xv[8], yv[8], zv[8], dist[8];
#pragma unroll
    for (int k = 0; k < 8; ++k) {
        int n = t + k*512;
        xv[k] = X[n]; yv[k] = X[NN+n]; zv[k] = X[2*NN+n];
        pts4[n] = make_float4(-xv[k], -yv[k], -zv[k], 0.0f);
        dist[k] = 1e10f;
    }
    unsigned long long px2[4], py2[4], pz2[4];
#pragma unroll
    for (int j = 0; j < 4; ++j) {
        px2[j] = pack2(xv[2*j], xv[2*j+1]);
        py2[j] = pack2(yv[2*j], yv[2*j+1]);
        pz2[j] = pack2(zv[2*j], zv[2*j+1]);
    }
    __syncthreads();

    int far = 0;
    for (int s = 0; s < SS; ++s) {
        float4 cn = pts4[far];             // negated centroid (broadcast LDS.128)
        if (t == 0) cbuf[s] = cn;
        unsigned long long cx2 = pack2(cn.x, cn.x);
        unsigned long long cy2 = pack2(cn.y, cn.y);
        unsigned long long cz2 = pack2(cn.z, cn.z);
#pragma unroll
        for (int j = 0; j < 4; ++j) {
            unsigned long long dx2 = add2(px2[j], cx2);   // p + (-c) == p - c
            unsigned long long dy2 = add2(py2[j], cy2);
            unsigned long long dz2 = add2(pz2[j], cz2);
            unsigned long long d2 = mul2(dx2, dx2);
            d2 = fma2(dy2, dy2, d2);
            d2 = fma2(dz2, dz2, d2);
            float2 dd = unpack2(d2);
            dist[2*j]   = fminf(dist[2*j],   dd.x);
            dist[2*j+1] = fminf(dist[2*j+1], dd.y);
        }
        // tree argmax over 8 (strict > keeps lowest k = lowest global index)
        float v0 = dist[0]; int q0 = 0;
        if (dist[1] > v0) { v0 = dist[1]; q0 = 1; }
        float v1 = dist[2]; int q1 = 2;
        if (dist[3] > v1) { v1 = dist[3]; q1 = 3; }
        float v2 = dist[4]; int q2 = 4;
        if (dist[5] > v2) { v2 = dist[5]; q2 = 5; }
        float v3 = dist[6]; int q3 = 6;
        if (dist[7] > v3) { v3 = dist[7]; q3 = 7; }
        if (v1 > v0) { v0 = v1; q0 = q1; }
        if (v3 > v2) { v2 = v3; q2 = q3; }
        if (v2 > v0) { v0 = v2; q0 = q2; }
        int mi = t + q0*512;

        unsigned db = __float_as_uint(v0);  // >= 0: bits order-preserving
        unsigned wm = __reduce_max_sync(0xFFFFFFFFu, db);
        unsigned lo = __reduce_max_sync(0xFFFFFFFFu, (db == wm) ? ~(unsigned)mi : 0u);
        if (lane == 0) wkey[s & 1][wid] = ((unsigned long long)wm << 32) | lo;
        __syncthreads();
        unsigned long long k2 = wkey[s & 1][lane & 15];
        unsigned hi = (unsigned)(k2 >> 32), l2v = (unsigned)k2;
        unsigned m2 = __reduce_max_sync(0xFFFFFFFFu, hi);
        unsigned lw = __reduce_max_sync(0xFFFFFFFFu, (hi == m2) ? l2v : 0u);
        far = (int)(~lw);
    }
    __syncthreads();
    {   // coalesced centroid dump: thread t handles s = t (SS == blockDim)
        float4 cn = cbuf[t];
        float cx = -cn.x, cy = -cn.y, cz = -cn.z;
        out_newxyz[(b*3+0)*SS + t] = cx;
        out_newxyz[(b*3+1)*SS + t] = cy;
        out_newxyz[(b*3+2)*SS + t] = cz;
        float sn = fmaf(cz,cz,fmaf(cy,cy,cx*cx));
        g_new[b*SS+t] = make_float4(cx,cy,cz,sn);
    }
}

// Ball query + gather + fused 27-moment accumulation. One warp per centroid.
__global__ __launch_bounds__(256) void group_kernel(const float* __restrict__ xyz,
                                                    const float* __restrict__ pts)
{
    __shared__ int sel[8][NSAMP];
    __shared__ float red[27];
    const int lane = threadIdx.x & 31, w = threadIdx.x >> 5;
    const int tid = threadIdx.x;
    if (tid < 27) red[tid] = 0.0f;
    __syncthreads();

    const int id = blockIdx.x*8 + w;
    const int b = id >> 9;
    const float4 c4 = g_new[id];
    const float* X = xyz + b*3*NN;
    const float* Q = pts + b*3*NN;
    const float R2 = (float)(0.4*0.4);

    int cnt = 0;
    for (int base = 0; base < NN && cnt < NSAMP; base += 32) {
        int n = base + lane;
        float x = X[n], y = X[NN+n], z = X[2*NN+n];
        float sx  = fmaf(z,z,fmaf(y,y,x*x));
        float dot = fmaf(z,c4.z,fmaf(y,c4.y,x*c4.x));
        float sq  = (c4.w + sx) - 2.0f*dot;
        bool pred = (sq <= R2);
        unsigned m = __ballot_sync(0xFFFFFFFFu, pred);
        if (pred) {
            int pos = cnt + __popc(m & ((1u << lane) - 1u));
            if (pos < NSAMP) sel[w][pos] = n;
        }
        cnt += __popc(m);
    }
    __syncwarp();
    int total = cnt < NSAMP ? cnt : NSAMP;
    int idx = sel[w][lane < total ? lane : 0];

    float f[6];
    f[0] = X[idx]      - c4.x;
    f[1] = X[NN+idx]   - c4.y;
    f[2] = X[2*NN+idx] - c4.z;
    f[3] = Q[idx];
    f[4] = Q[NN+idx];
    f[5] = Q[2*NN+idx];

    int p = id*NSAMP + lane;
#pragma unroll
    for (int c = 0; c < 6; ++c) g_feat[c*PPOS + p] = f[c];

    float v[27];
#pragma unroll
    for (int c = 0; c < 6; ++c) v[c] = f[c];
    {
        int k = 6;
#pragma unroll
        for (int i = 0; i < 6; ++i)
#pragma unroll
            for (int j = i; j < 6; ++j) { v[k] = f[i]*f[j]; ++k; }
    }
#pragma unroll
    for (int off = 16; off; off >>= 1)
#pragma unroll
        for (int i = 0; i < 27; ++i)
            v[i] += __shfl_down_sync(0xFFFFFFFFu, v[i], off);
    if (lane == 0)
#pragma unroll
        for (int i = 0; i < 27; ++i) atomicAdd(&red[i], v[i]);
    __syncthreads();
    if (tid < 27) atomicAdd(&g_gram[tid*32], red[tid]);
}

// PERSISTENT fused layer1+layer2: weights + BN1 loaded once, tiles looped.
__global__ __launch_bounds__(256,2) void fused12_kernel(const float* __restrict__ w0,
                                                        const float* __restrict__ b0,
                                                        const float* __restrict__ g0,
                                                        const float* __restrict__ beta0,
                                                        const float* __restrict__ w1,
                                                        const float* __restrict__ b1)
{
    extern __shared__ char smraw[];
    unsigned long long* w0d = (unsigned long long*)smraw;            // 384 ull
    unsigned long long* w1d = (unsigned long long*)(smraw + 3072);   // 4096 ull
    float* sab = (float*)(smraw + 35840);                            // 128 (BN1 A/B)
    float* tf  = (float*)(smraw + 36352);                            // 6 x 256
    float* tx  = (float*)(smraw + 42496);                            // 64 x 256
    float* red = (float*)(smraw + 108032);                           // 128 (BN2 partials)
    const int tid  = threadIdx.x;
    const int lane = tid & 31, wid = tid >> 5;
    const int ob = wid * 8;

    if (tid < 128) red[tid] = 0.0f;
    if (tid < 64) {
        const int o = tid;
        float w[6];
#pragma unroll
        for (int c = 0; c < 6; ++c) w[c] = w0[o*6+c];
        float wS = 0.0f;
#pragma unroll
        for (int c = 0; c < 6; ++c) wS = fmaf(w[c], g_gram[c*32], wS);
        float quad = 0.0f; int idx = 6;
#pragma unroll
        for (int i = 0; i < 6; ++i)
#pragma unroll
            for (int j = i; j < 6; ++j) {
                float coef = (i == j) ? 1.0f : 2.0f;
                quad = fmaf(coef * w[i] * w[j], g_gram[idx*32], quad);
                ++idx;
            }
        float bo = b0[o];
        const float invP = 1.0f / (float)PPOS;
        float m   = fmaf(wS, invP, bo);
        float Ex2 = quad*invP + 2.0f*bo*wS*invP + bo*bo;
        float A = g0[o] * rsqrtf(Ex2 - m*m + 1e-5f);
        sab[o]    = A;
        sab[64+o] = fmaf(bo - m, A, beta0[o]);
    }
    for (int i = tid; i < 384; i += 256) { float v = w0[i]; w0d[i] = pack2(v,v); }
    for (int i = tid; i < 1024; i += 256) {
        float4 v = ((const float4*)w1)[i];
        w1d[i*4+0] = pack2(v.x,v.x); w1d[i*4+1] = pack2(v.y,v.y);
        w1d[i*4+2] = pack2(v.z,v.z); w1d[i*4+3] = pack2(v.w,v.w);
    }

    for (int tile = blockIdx.x; tile < PPOS/256; tile += NPERS) {
        const int p0 = tile * 256;
        __syncthreads();
        for (int i = tid; i < 384; i += 256) {
            int c = i >> 6, pp = (i & 63) * 4;
            *(float4*)(tf + c*256 + pp) = *(const float4*)(g_feat + c*PPOS + p0 + pp);
        }
        __syncthreads();

        // ---- stage A: 6 -> 64 ----
        {
            unsigned long long a[8][4];
#pragma unroll
            for (int j = 0; j < 8; ++j)
#pragma unroll
                for (int q = 0; q < 4; ++q) a[j][q] = 0ull;
#pragma unroll
            for (int c = 0; c < 6; ++c) {
                ulonglong2 iv0 = *(const ulonglong2*)(tf + c*256 + lane*4);
                ulonglong2 iv1 = *(const ulonglong2*)(tf + c*256 + 128 + lane*4);
#pragma unroll
                for (int j = 0; j < 8; ++j) {
                    unsigned long long wv = w0d[(ob+j)*6 + c];
                    a[j][0] = fma2(wv, iv0.x, a[j][0]);
                    a[j][1] = fma2(wv, iv0.y, a[j][1]);
                    a[j][2] = fma2(wv, iv1.x, a[j][2]);
                    a[j][3] = fma2(wv, iv1.y, a[j][3]);
                }
            }
#pragma unroll
            for (int j = 0; j < 8; ++j) {
                float A = sab[ob+j], Bv = sab[64+ob+j];
#pragma unroll
                for (int s2 = 0; s2 < 2; ++s2) {
                    float2 u = unpack2(a[j][s2*2+0]);
                    float2 v = unpack2(a[j][s2*2+1]);
                    float4 o4;
                    o4.x = fmaxf(fmaf(u.x,A,Bv),0.f);
                    o4.y = fmaxf(fmaf(u.y,A,Bv),0.f);
                    o4.z = fmaxf(fmaf(v.x,A,Bv),0.f);
                    o4.w = fmaxf(fmaf(v.y,A,Bv),0.f);
                    *(float4*)(tx + (ob+j)*256 + s2*128 + lane*4) = o4;
                }
            }
        }
        __syncthreads();

        // ---- stage B: 64 -> 64 ----
        unsigned long long acc[8][4];
#pragma unroll
        for (int j = 0; j < 8; ++j) {
            float bv = b1[ob+j];
            unsigned long long pb = pack2(bv,bv);
#pragma unroll
            for (int q = 0; q < 4; ++q) acc[j][q] = pb;
        }
#pragma unroll 4
        for (int c2 = 0; c2 < 32; ++c2) {
            const float* base = tx + c2*512;
            ulonglong2 a0 = *(const ulonglong2*)(base + lane*4);
            ulonglong2 a1 = *(const ulonglong2*)(base + 128 + lane*4);
            ulonglong2 c0 = *(const ulonglong2*)(base + 256 + lane*4);
            ulonglong2 c1 = *(const ulonglong2*)(base + 384 + lane*4);
#pragma unroll
            for (int j = 0; j < 8; ++j) {
                ulonglong2 wp = *(const ulonglong2*)(w1d + (ob+j)*64 + c2*2);
                acc[j][0] = fma2(wp.x, a0.x, acc[j][0]);
                acc[j][1] = fma2(wp.x, a0.y, acc[j][1]);
                acc[j][2] = fma2(wp.x, a1.x, acc[j][2]);
                acc[j][3] = fma2(wp.x, a1.y, acc[j][3]);
                acc[j][0] = fma2(wp.y, c0.x, acc[j][0]);
                acc[j][1] = fma2(wp.y, c0.y, acc[j][1]);
                acc[j][2] = fma2(wp.y, c1.x, acc[j][2]);
                acc[j][3] = fma2(wp.y, c1.y, acc[j][3]);
            }
        }
#pragma unroll
        for (int j = 0; j < 8; ++j) {
            float2 u0 = unpack2(acc[j][0]), u1 = unpack2(acc[j][1]);
            float2 v0 = unpack2(acc[j][2]), v1 = unpack2(acc[j][3]);
            float4 o0 = make_float4(u0.x,u0.y,u1.x,u1.y);
            float4 o1 = make_float4(v0.x,v0.y,v1.x,v1.y);
            *(float4*)(g_x2 + (size_t)(ob+j)*PPOS + p0 + lane*4)       = o0;
            *(float4*)(g_x2 + (size_t)(ob+j)*PPOS + p0 + 128 + lane*4) = o1;
            float sm1 = ((o0.x+o0.y)+(o0.z+o0.w)) + ((o1.x+o1.y)+(o1.z+o1.w));
            float sq  = o0.x*o0.x+o0.y*o0.y+o0.z*o0.z+o0.w*o0.w
                      + o1.x*o1.x+o1.y*o1.y+o1.z*o1.z+o1.w*o1.w;
#pragma unroll
            for (int off = 16; off; off >>= 1) {
                sm1 += __shfl_down_sync(0xFFFFFFFFu, sm1, off);
                sq  += __shfl_down_sync(0xFFFFFFFFu, sq,  off);
            }
            if (lane == 0) {
                red[ob+j]    += sm1;
                red[64+ob+j] += sq;
            }
        }
    }
    __syncthreads();
    if (tid < 128) atomicAdd(&g_stats[tid], red[tid]);
}

// PERSISTENT layer3 (64->128): weights once, cp.async-pipelined x2 tiles,
// inline BN2 fold, smem BN3 stat accumulation, {max,min} pooling.
__global__ __launch_bounds__(256,2) void mlp3_kernel(const float* __restrict__ w2,
                                                     const float* __restrict__ b2,
                                                     const float* __restrict__ g1,
                                                     const float* __restrict__ beta1)
{
    extern __shared__ char smraw[];
    unsigned long long* wd = (unsigned long long*)smraw;   // 8192 ull = 64KB
    float* sab = (float*)(smraw + 65536);                  // 128 (BN2 A/B)
    float* red = (float*)(smraw + 66048);                  // 256 (BN3 partials)
    float* tx  = (float*)(smraw + 67072);                  // 64 x 128 = 32KB
    const int tid  = threadIdx.x;
    const int lane = tid & 31, wid = tid >> 5;
    const int ob = wid * 16;

    red[tid] = 0.0f;
    if (tid < 64) {
        const float invP = 1.0f / (float)PPOS;
        float mean = g_stats[tid]    * invP;
        float var  = g_stats[64+tid] * invP - mean*mean;
        float A = g1[tid] * rsqrtf(var + 1e-5f);
        sab[tid]    = A;
        sab[64+tid] = fmaf(-mean, A, beta1[tid]);
    }
    for (int i = tid; i < 2048; i += 256) {
        float4 v = ((const float4*)w2)[i];
        wd[i*4+0] = pack2(v.x,v.x); wd[i*4+1] = pack2(v.y,v.y);
        wd[i*4+2] = pack2(v.z,v.z); wd[i*4+3] = pack2(v.w,v.w);
    }

    int tile = blockIdx.x;
#pragma unroll
    for (int k = 0; k < 8; ++k) {
        int i = tid + k*256;
        int c = i >> 5, pp = (i & 31) * 4;
        cp_async16(tx + c*128 + pp, g_x2 + (size_t)c*PPOS + tile*128 + pp);
    }
    cp_commit(); cp_wait0();
    __syncthreads();

    while (tile < PPOS/128) {
        for (int k = 0; k < 8; ++k) {
            int i = tid + k*256;
            int c = i >> 5, pp = (i & 31) * 4;
            float A = sab[c], Bv = sab[64+c];
            float4 v = *(float4*)(tx + c*128 + pp);
            v.x = fmaxf(fmaf(v.x,A,Bv),0.f); v.y = fmaxf(fmaf(v.y,A,Bv),0.f);
            v.z = fmaxf(fmaf(v.z,A,Bv),0.f); v.w = fmaxf(fmaf(v.w,A,Bv),0.f);
            *(float4*)(tx + c*128 + pp) = v;
        }
        __syncthreads();

        unsigned long long acc[16][2];
#pragma unroll
        for (int j = 0; j < 16; ++j) {
            float bv = b2[ob+j];
            unsigned long long pb = pack2(bv,bv);
            acc[j][0] = pb; acc[j][1] = pb;
        }
#pragma unroll 4
        for (int c2 = 0; c2 < 32; ++c2) {
            const float* base = tx + c2*256;
            ulonglong2 d0 = *(const ulonglong2*)(base + lane*4);
            ulonglong2 d1 = *(const ulonglong2*)(base + 128 + lane*4);
#pragma unroll
            for (int j = 0; j < 16; ++j) {
                ulonglong2 wp = *(const ulonglong2*)(wd + (ob+j)*64 + c2*2);
                acc[j][0] = fma2(wp.x, d0.x, acc[j][0]);
                acc[j][1] = fma2(wp.x, d0.y, acc[j][1]);
                acc[j][0] = fma2(wp.y, d1.x, acc[j][0]);
                acc[j][1] = fma2(wp.y, d1.y, acc[j][1]);
            }
        }
        __syncthreads();

        int next = tile + NPERS;
        if (next < PPOS/128) {
#pragma unroll
            for (int k = 0; k < 8; ++k) {
                int i = tid + k*256;
                int c = i >> 5, pp = (i & 31) * 4;
                cp_async16(tx + c*128 + pp, g_x2 + (size_t)c*PPOS + next*128 + pp);
            }
        }
        cp_commit();

#pragma unroll
        for (int j = 0; j < 16; ++j) {
            float2 u = unpack2(acc[j][0]), v = unpack2(acc[j][1]);
            float f0 = u.x, f1 = u.y, f2 = v.x, f3 = v.y;
            float sm1 = (f0+f1)+(f2+f3);
            float sq  = f0*f0+f1*f1+f2*f2+f3*f3;
#pragma unroll
            for (int off = 16; off; off >>= 1) {
                sm1 += __shfl_down_sync(0xFFFFFFFFu, sm1, off);
                sq  += __shfl_down_sync(0xFFFFFFFFu, sq,  off);
            }
            if (lane == 0) {
                red[ob+j]     += sm1;
                red[128+ob+j] += sq;
            }
            float mx = fmaxf(fmaxf(f0,f1), fmaxf(f2,f3));
            float mn = fminf(fminf(f0,f1), fminf(f2,f3));
#pragma unroll
            for (int dlt = 1; dlt < 8; dlt <<= 1) {
                mx = fmaxf(mx, __shfl_xor_sync(0xFFFFFFFFu, mx, dlt));
                mn = fminf(mn, __shfl_xor_sync(0xFFFFFFFFu, mn, dlt));
            }
            if ((lane & 7) == 0) {
                int gid = tile*4 + (lane >> 3);
                g_pool[(ob+j)*NGRP + gid] = make_float2(mx, mn);
            }
        }
        cp_wait0();
        __syncthreads();
        tile = next;
    }
    __syncthreads();
    atomicAdd(&g_stats[128 + tid], red[tid]);
}

// Final: inline BN3 fold + affine+relu on pooled max/min. One CTA per (b,o).
__global__ __launch_bounds__(256) void final_kernel(float* __restrict__ out,
                                                    const float* __restrict__ g2,
                                                    const float* __restrict__ beta2)
{
    __shared__ float sA, sB;
    const int o = blockIdx.x & 127;
    const int b = blockIdx.x >> 7;
    if (threadIdx.x == 0) {
        const float invP = 1.0f / (float)PPOS;
        float mean = g_stats[128+o] * invP;
        float var  = g_stats[256+o] * invP - mean*mean;
        float A = g2[o] * rsqrtf(var + 1e-5f);
        sA = A; sB = fmaf(-mean, A, beta2[o]);
    }
    __syncthreads();
    float A = sA, Bv = sB;
    int s = threadIdx.x * 2;
    float2 p0 = g_pool[o*NGRP + b*SS + s];
    float2 p1 = g_pool[o*NGRP + b*SS + s + 1];
    float v0 = (A >= 0.0f) ? p0.x : p0.y;
    float v1 = (A >= 0.0f) ? p1.x : p1.y;
    float2 r;
    r.x = fmaxf(fmaf(v0, A, Bv), 0.0f);
    r.y = fmaxf(fmaf(v1, A, Bv), 0.0f);
    *(float2*)(out + ((b*128 + o) << 9) + s) = r;
}

// ---------------- launch ----------------
extern "C" void kernel_launch(void* const* d_in, const int* in_sizes, int n_in,
                              void* d_out, int out_size)
{
    const float* xyz = (const float*)d_in[0];
    const float* pts = (const float*)d_in[1];
    const float* w0  = (const float*)d_in[2];
    const float* b0  = (const float*)d_in[3];
    const float* gm0 = (const float*)d_in[4];
    const float* be0 = (const float*)d_in[5];
    const float* w1  = (const float*)d_in[6];
    const float* b1  = (const float*)d_in[7];
    const float* gm1 = (const float*)d_in[8];
    const float* be1 = (const float*)d_in[9];
    const float* w2  = (const float*)d_in[10];
    const float* b2  = (const float*)d_in[11];
    const float* gm2 = (const float*)d_in[12];
    const float* be2 = (const float*)d_in[13];
    float* out = (float*)d_out;

    cudaFuncSetAttribute(fps_kernel,     cudaFuncAttributeMaxDynamicSharedMemorySize, 73728);
    cudaFuncSetAttribute(fused12_kernel, cudaFuncAttributeMaxDynamicSharedMemorySize, 108544);
    cudaFuncSetAttribute(mlp3_kernel,    cudaFuncAttributeMaxDynamicSharedMemorySize, 99840);

    fps_kernel<<<BB, 512, 73728>>>(xyz, out);
    group_kernel<<<(BB*SS)/8, 256>>>(xyz, pts);
    fused12_kernel<<<NPERS, 256, 108544>>>(w0, b0, gm0, be0, w1, b1);
    mlp3_kernel<<<NPERS, 256, 99840>>>(w2, b2, gm1, be1);
    final_kernel<<<BB*128, 256>>>(out + BB*3*SS, gm2, be2);
}